// round 3
// baseline (speedup 1.0000x reference)
#include <cuda_runtime.h>
#include <cuda_bf16.h>
#include <cstdint>

// ============================================================================
// Problem constants
// ============================================================================
#define NQ        1024        // queries (B)
#define DDIM      512         // feature dim (K of GEMM)
#define MROWS     262144      // memory bank rows
#define BANK_TILE 128         // bank rows per CTA
#define NQG       8           // query groups of 128
#define NCHUNK    64          // 8 qg x 8 k-chunks of 64

// smem layout (bytes). Bank rows padded 1024->1040 so 8-row ldmatrix strides
// land on distinct bank groups (1040 mod 128 == 16). Query rows 128->144.
#define BANK_RS    1040
#define QBUF_RS    144
#define SMEM_BANK  0
#define BANK_SZ    (BANK_TILE * BANK_RS)          // 133120
#define SMEM_QBUF  BANK_SZ
#define QBUF_SZ    (128 * QBUF_RS)                // 18432
#define SMEM_TOTAL (SMEM_QBUF + 2 * QBUF_SZ)      // 169984

// ============================================================================
// Scratch globals (allocation-free rule)
// ============================================================================
__device__ __align__(1024) __nv_bfloat16 g_qbf[NQ * DDIM];  // normalized bf16 queries
__device__ unsigned g_key[NQ];                               // ordered-uint max keys

// ============================================================================
// Helpers
// ============================================================================
__device__ __forceinline__ uint32_t smem_to_u32(const void* p) {
    uint32_t a;
    asm("{ .reg .u64 t; cvta.to.shared.u64 t, %1; cvt.u32.u64 %0, t; }" : "=r"(a) : "l"(p));
    return a;
}

#define CP_ASYNC16(dst_u32, src_gptr) \
    asm volatile("cp.async.cg.shared.global [%0], [%1], 16;" :: "r"(dst_u32), "l"(src_gptr) : "memory")
#define CP_ASYNC_COMMIT() asm volatile("cp.async.commit_group;" ::: "memory")
#define CP_ASYNC_WAIT(n)  asm volatile("cp.async.wait_group %0;" :: "n"(n) : "memory")

#define LDMATRIX_X4(r0, r1, r2, r3, addr) \
    asm volatile("ldmatrix.sync.aligned.m8n8.x4.shared.b16 {%0,%1,%2,%3}, [%4];" \
        : "=r"(r0), "=r"(r1), "=r"(r2), "=r"(r3) : "r"(addr))

__device__ __forceinline__ void mma16816(float* d, const uint32_t* a, uint32_t b0, uint32_t b1) {
    asm volatile(
        "mma.sync.aligned.m16n8k16.row.col.f32.bf16.bf16.f32 "
        "{%0,%1,%2,%3}, {%4,%5,%6,%7}, {%8,%9}, {%0,%1,%2,%3};"
        : "+f"(d[0]), "+f"(d[1]), "+f"(d[2]), "+f"(d[3])
        : "r"(a[0]), "r"(a[1]), "r"(a[2]), "r"(a[3]), "r"(b0), "r"(b1));
}

// ============================================================================
// Kernel 1: normalize queries -> bf16 buffer; init max keys
// ============================================================================
__global__ void __launch_bounds__(128) prep_kernel(const float* __restrict__ feat) {
    const int b = blockIdx.x;
    const int tid = threadIdx.x;
    const float4* row = reinterpret_cast<const float4*>(feat + (size_t)b * DDIM);
    float4 v = row[tid];
    float ss = v.x * v.x + v.y * v.y + v.z * v.z + v.w * v.w;
    #pragma unroll
    for (int o = 16; o > 0; o >>= 1) ss += __shfl_xor_sync(0xFFFFFFFFu, ss, o);
    __shared__ float ws[4];
    if ((tid & 31) == 0) ws[tid >> 5] = ss;
    __syncthreads();
    float inv = rsqrtf(ws[0] + ws[1] + ws[2] + ws[3]);
    __nv_bfloat162* out = reinterpret_cast<__nv_bfloat162*>(g_qbf + (size_t)b * DDIM);
    out[tid * 2 + 0] = __floats2bfloat162_rn(v.x * inv, v.y * inv);
    out[tid * 2 + 1] = __floats2bfloat162_rn(v.z * inv, v.w * inv);
    if (tid == 0) g_key[b] = 0u;
}

// ============================================================================
// Kernel 2: fused GEMM (mma.sync bf16) + max epilogue.
//   CTA: 128 bank rows x 1024 queries. 8 warps; warp w owns query rows
//   [w*16, w*16+16) of each 128-query group, and all 16 n8 bank tiles.
//   Max over bank rows folds in registers -> 2 shuffles -> atomicMax.
// ============================================================================
__global__ void __launch_bounds__(256, 1) patchcore_main(const float* __restrict__ bank) {
    extern __shared__ char smem[];
    const uint32_t sb = smem_to_u32(smem);
    const int tid  = threadIdx.x;
    const int w    = tid >> 5;
    const int lane = tid & 31;
    const size_t m0 = (size_t)blockIdx.x * BANK_TILE;

    // ---- Load bank tile (128 x 512 fp32), convert bf16, store padded rows ----
    {
        const float4* src = reinterpret_cast<const float4*>(bank);
        #pragma unroll 4
        for (int idx = tid; idx < BANK_TILE * (DDIM / 4); idx += 256) {
            int m = idx >> 7;           // bank row within tile
            int c4 = idx & 127;         // float4 index within row
            float4 v = src[((m0 + (size_t)m) << 7) + c4];
            __nv_bfloat162 lo = __floats2bfloat162_rn(v.x, v.y);
            __nv_bfloat162 hi = __floats2bfloat162_rn(v.z, v.w);
            uint2 p;
            p.x = *reinterpret_cast<uint32_t*>(&lo);
            p.y = *reinterpret_cast<uint32_t*>(&hi);
            *reinterpret_cast<uint2*>(smem + (SMEM_BANK + m * BANK_RS + c4 * 8)) = p;
        }
    }
    __syncthreads();

    // ldmatrix lane address components (canonical x4 pattern)
    const uint32_t lm_row = (uint32_t)(lane & 15);
    const uint32_t lm_col = (uint32_t)((lane & 16) ? 16 : 0);
    const uint32_t a_lane = lm_row * QBUF_RS + lm_col + (uint32_t)(w * 16 * QBUF_RS);
    const uint32_t b_lane = sb + SMEM_BANK + lm_row * BANK_RS + lm_col;

    const char* qbase = reinterpret_cast<const char*>(g_qbf);

    // cp.async loader: chunk j = qg*8 + kc (128 queries x 64 dims) into buf
    auto issue_qchunk = [&](int j, int buf) {
        int qg = j >> 3, kc = j & 7;
        const char* src_base = qbase + (size_t)(qg * 128) * 1024 + kc * 128;
        uint32_t dst_base = sb + (uint32_t)(SMEM_QBUF + buf * QBUF_SZ);
        #pragma unroll
        for (int it = 0; it < 4; ++it) {
            int idx = tid + it * 256;   // 1024 granules of 16B
            int n = idx >> 3, t = idx & 7;
            CP_ASYNC16(dst_base + (uint32_t)(n * QBUF_RS + t * 16),
                       src_base + (size_t)n * 1024 + t * 16);
        }
        CP_ASYNC_COMMIT();
    };

    issue_qchunk(0, 0);
    int j = 0;
    for (int g = 0; g < NQG; ++g) {
        float d[16][4];
        #pragma unroll
        for (int nt = 0; nt < 16; ++nt)
            #pragma unroll
            for (int e = 0; e < 4; ++e) d[nt][e] = 0.0f;

        for (int kc = 0; kc < 8; ++kc, ++j) {
            const int buf = j & 1;
            if (j + 1 < NCHUNK) {
                issue_qchunk(j + 1, buf ^ 1);
                CP_ASYNC_WAIT(1);
            } else {
                CP_ASYNC_WAIT(0);
            }
            __syncthreads();

            const uint32_t abase = sb + (uint32_t)(SMEM_QBUF + buf * QBUF_SZ) + a_lane;
            const uint32_t bbase = b_lane + (uint32_t)(kc * 128);
            #pragma unroll
            for (int ks = 0; ks < 4; ++ks) {
                uint32_t a[4];
                LDMATRIX_X4(a[0], a[1], a[2], a[3], abase + (uint32_t)(ks * 32));
                #pragma unroll
                for (int np = 0; np < 8; ++np) {
                    uint32_t b0, b1, b2, b3;   // b0/b2: n-tile 2np ; b1/b3: 2np+1
                    LDMATRIX_X4(b0, b1, b2, b3,
                                bbase + (uint32_t)(np * 16 * BANK_RS + ks * 32));
                    mma16816(d[2 * np],     a, b0, b2);
                    mma16816(d[2 * np + 1], a, b1, b3);
                }
            }
            __syncthreads();   // all warps done reading buf before it is refilled
        }

        // ---- Epilogue: max over 128 bank rows for this query group ----
        float mx0 = -3.0e38f, mx1 = -3.0e38f;   // query rows r and r+8
        #pragma unroll
        for (int nt = 0; nt < 16; ++nt) {
            mx0 = fmaxf(mx0, fmaxf(d[nt][0], d[nt][1]));
            mx1 = fmaxf(mx1, fmaxf(d[nt][2], d[nt][3]));
        }
        mx0 = fmaxf(mx0, __shfl_xor_sync(0xFFFFFFFFu, mx0, 1));
        mx0 = fmaxf(mx0, __shfl_xor_sync(0xFFFFFFFFu, mx0, 2));
        mx1 = fmaxf(mx1, __shfl_xor_sync(0xFFFFFFFFu, mx1, 1));
        mx1 = fmaxf(mx1, __shfl_xor_sync(0xFFFFFFFFu, mx1, 2));
        if ((lane & 3) == 0) {
            int q0 = g * 128 + w * 16 + (lane >> 2);
            unsigned k0 = __float_as_uint(mx0);
            k0 = (k0 & 0x80000000u) ? ~k0 : (k0 | 0x80000000u);
            unsigned k1 = __float_as_uint(mx1);
            k1 = (k1 & 0x80000000u) ? ~k1 : (k1 | 0x80000000u);
            atomicMax(&g_key[q0], k0);
            atomicMax(&g_key[q0 + 8], k1);
        }
    }
}

// ============================================================================
// Kernel 3: decode keys -> min distances
// ============================================================================
__global__ void final_kernel(float* __restrict__ out) {
    int b = blockIdx.x * blockDim.x + threadIdx.x;
    if (b < NQ) {
        unsigned key = g_key[b];
        unsigned bits = (key & 0x80000000u) ? (key ^ 0x80000000u) : ~key;
        float xy = __uint_as_float(bits);
        out[b] = sqrtf(fmaxf(2.0f - 2.0f * xy, 1e-12f));
    }
}

// ============================================================================
// Launch
// ============================================================================
extern "C" void kernel_launch(void* const* d_in, const int* in_sizes, int n_in,
                              void* d_out, int out_size) {
    const float* feat = (const float*)d_in[0];
    const float* bank = (const float*)d_in[1];
    if (n_in >= 2 && in_sizes[0] != NQ * DDIM) {   // robust to input ordering
        feat = (const float*)d_in[1];
        bank = (const float*)d_in[0];
    }
    float* out = (float*)d_out;

    cudaFuncSetAttribute(patchcore_main, cudaFuncAttributeMaxDynamicSharedMemorySize, SMEM_TOTAL);

    prep_kernel<<<NQ, 128>>>(feat);
    patchcore_main<<<MROWS / BANK_TILE, 256, SMEM_TOTAL>>>(bank);
    final_kernel<<<1, NQ>>>(out);
}

// round 4
// speedup vs baseline: 1.0581x; 1.0581x over previous
#include <cuda_runtime.h>
#include <cuda_bf16.h>
#include <cstdint>

// ============================================================================
// Problem constants
// ============================================================================
#define NQ        1024        // queries (B)
#define DDIM      512         // feature dim (K)
#define MROWS     262144      // memory bank rows
#define BANK_TILE 128         // bank rows per CTA
#define MEGA      256         // queries per pass
#define NPASS     4           // NQ / MEGA
#define KCH       8           // k-chunks of 64 per pass
#define NCHUNK    (NPASS * KCH)

// smem layout (bytes). Rows padded so 8-row ldmatrix strides hit distinct
// bank groups (pad mod 128 == 16).
#define BANK_RS    1040
#define QBUF_RS    144
#define SMEM_BANK  0
#define BANK_SZ    (BANK_TILE * BANK_RS)          // 133120
#define SMEM_QBUF  BANK_SZ
#define QBUF_SZ    (MEGA * QBUF_RS)               // 36864
#define SMEM_TOTAL (SMEM_QBUF + 2 * QBUF_SZ)      // 206848

// ============================================================================
// Scratch globals (allocation-free rule)
// ============================================================================
__device__ __align__(1024) __nv_bfloat16 g_qbf[NQ * DDIM];  // normalized bf16 queries
__device__ unsigned g_key[NQ];                               // ordered-uint max keys

// ============================================================================
// Helpers
// ============================================================================
__device__ __forceinline__ uint32_t smem_to_u32(const void* p) {
    uint32_t a;
    asm("{ .reg .u64 t; cvta.to.shared.u64 t, %1; cvt.u32.u64 %0, t; }" : "=r"(a) : "l"(p));
    return a;
}

#define CP_ASYNC16(dst_u32, src_gptr) \
    asm volatile("cp.async.cg.shared.global [%0], [%1], 16;" :: "r"(dst_u32), "l"(src_gptr) : "memory")
#define CP_ASYNC_COMMIT() asm volatile("cp.async.commit_group;" ::: "memory")
#define CP_ASYNC_WAIT(n)  asm volatile("cp.async.wait_group %0;" :: "n"(n) : "memory")

#define LDMATRIX_X4(r0, r1, r2, r3, addr) \
    asm volatile("ldmatrix.sync.aligned.m8n8.x4.shared.b16 {%0,%1,%2,%3}, [%4];" \
        : "=r"(r0), "=r"(r1), "=r"(r2), "=r"(r3) : "r"(addr))

__device__ __forceinline__ void mma16816(float* d, const uint32_t* a, uint32_t b0, uint32_t b1) {
    asm volatile(
        "mma.sync.aligned.m16n8k16.row.col.f32.bf16.bf16.f32 "
        "{%0,%1,%2,%3}, {%4,%5,%6,%7}, {%8,%9}, {%0,%1,%2,%3};"
        : "+f"(d[0]), "+f"(d[1]), "+f"(d[2]), "+f"(d[3])
        : "r"(a[0]), "r"(a[1]), "r"(a[2]), "r"(a[3]), "r"(b0), "r"(b1));
}

// ============================================================================
// Kernel 1: normalize queries -> bf16 buffer; init max keys
// ============================================================================
__global__ void __launch_bounds__(128) prep_kernel(const float* __restrict__ feat) {
    const int b = blockIdx.x;
    const int tid = threadIdx.x;
    const float4* row = reinterpret_cast<const float4*>(feat + (size_t)b * DDIM);
    float4 v = row[tid];
    float ss = v.x * v.x + v.y * v.y + v.z * v.z + v.w * v.w;
    #pragma unroll
    for (int o = 16; o > 0; o >>= 1) ss += __shfl_xor_sync(0xFFFFFFFFu, ss, o);
    __shared__ float ws[4];
    if ((tid & 31) == 0) ws[tid >> 5] = ss;
    __syncthreads();
    float inv = rsqrtf(ws[0] + ws[1] + ws[2] + ws[3]);
    __nv_bfloat162* out = reinterpret_cast<__nv_bfloat162*>(g_qbf + (size_t)b * DDIM);
    out[tid * 2 + 0] = __floats2bfloat162_rn(v.x * inv, v.y * inv);
    out[tid * 2 + 1] = __floats2bfloat162_rn(v.z * inv, v.w * inv);
    if (tid == 0) g_key[b] = 0u;
}

// ============================================================================
// Kernel 2: fused GEMM (mma.sync bf16) + max epilogue.
//   CTA: 128 bank rows x 1024 queries, 4 passes of 256 queries.
//   Warp grid 4(M) x 2(N): warp tile m64 x n64 -> 128 fp32 accum regs.
//   Max over bank rows folds in registers -> 2 shuffles -> atomicMax.
// ============================================================================
__global__ void __launch_bounds__(256, 1) patchcore_main(const float* __restrict__ bank) {
    extern __shared__ char smem[];
    const uint32_t sb = smem_to_u32(smem);
    const int tid  = threadIdx.x;
    const int w    = tid >> 5;
    const int lane = tid & 31;
    const int wm   = w & 3;        // 0..3 : m-offset wm*64
    const int wn   = w >> 2;       // 0..1 : n-offset wn*64
    const size_t m0 = (size_t)blockIdx.x * BANK_TILE;

    // ---- Load bank tile (128 x 512 fp32), convert bf16, store padded rows ----
    {
        const float4* src = reinterpret_cast<const float4*>(bank);
        #pragma unroll 4
        for (int idx = tid; idx < BANK_TILE * (DDIM / 4); idx += 256) {
            int m = idx >> 7;           // bank row within tile
            int c4 = idx & 127;         // float4 index within row
            float4 v = src[((m0 + (size_t)m) << 7) + c4];
            __nv_bfloat162 lo = __floats2bfloat162_rn(v.x, v.y);
            __nv_bfloat162 hi = __floats2bfloat162_rn(v.z, v.w);
            uint2 p;
            p.x = *reinterpret_cast<uint32_t*>(&lo);
            p.y = *reinterpret_cast<uint32_t*>(&hi);
            *reinterpret_cast<uint2*>(smem + (SMEM_BANK + m * BANK_RS + c4 * 8)) = p;
        }
    }
    __syncthreads();

    // ldmatrix lane addressing (canonical x4: rows lane&15, k-half by lane&16)
    const uint32_t lm_row = (uint32_t)(lane & 15);
    const uint32_t lm_col = (uint32_t)((lane & 16) ? 16 : 0);
    // A: query rows wm*64 + mt*16 + lm_row, within current chunk buffer
    const uint32_t a_lane = (uint32_t)((wm * 64) + lm_row) * QBUF_RS + lm_col;
    // B: bank rows wn*64 + bt*16 + lm_row
    const uint32_t b_lane = sb + SMEM_BANK +
                            ((uint32_t)(wn * 64) + lm_row) * BANK_RS + lm_col;

    const char* qbase = reinterpret_cast<const char*>(g_qbf);

    // cp.async loader: chunk j = pass*8 + kc (256 queries x 64 dims) into buf
    auto issue_qchunk = [&](int j, int buf) {
        int pass = j >> 3, kc = j & 7;
        const char* src_base = qbase + (size_t)(pass * MEGA) * 1024 + kc * 128;
        uint32_t dst_base = sb + (uint32_t)(SMEM_QBUF + buf * QBUF_SZ);
        #pragma unroll
        for (int it = 0; it < 8; ++it) {
            int idx = tid + it * 256;   // 2048 granules of 16B
            int n = idx >> 3, t = idx & 7;
            CP_ASYNC16(dst_base + (uint32_t)(n * QBUF_RS + t * 16),
                       src_base + (size_t)n * 1024 + t * 16);
        }
        CP_ASYNC_COMMIT();
    };

    issue_qchunk(0, 0);
    int j = 0;
    for (int pass = 0; pass < NPASS; ++pass) {
        float d[4][8][4];               // [m-tile][n-tile][frag] = 128 regs
        #pragma unroll
        for (int mt = 0; mt < 4; ++mt)
            #pragma unroll
            for (int nt = 0; nt < 8; ++nt)
                #pragma unroll
                for (int e = 0; e < 4; ++e) d[mt][nt][e] = 0.0f;

        for (int kc = 0; kc < KCH; ++kc, ++j) {
            const int buf = j & 1;
            if (j + 1 < NCHUNK) {
                issue_qchunk(j + 1, buf ^ 1);
                CP_ASYNC_WAIT(1);
            } else {
                CP_ASYNC_WAIT(0);
            }
            __syncthreads();

            const uint32_t abase = sb + (uint32_t)(SMEM_QBUF + buf * QBUF_SZ) + a_lane;
            const uint32_t bbase = b_lane + (uint32_t)(kc * 128);
            #pragma unroll
            for (int ks = 0; ks < 4; ++ks) {
                uint32_t a[4][4];
                #pragma unroll
                for (int mt = 0; mt < 4; ++mt)
                    LDMATRIX_X4(a[mt][0], a[mt][1], a[mt][2], a[mt][3],
                                abase + (uint32_t)(mt * 16 * QBUF_RS + ks * 32));
                #pragma unroll
                for (int bt = 0; bt < 4; ++bt) {
                    uint32_t b0, b1, b2, b3;   // b0/b2: n-tile 2bt ; b1/b3: 2bt+1
                    LDMATRIX_X4(b0, b1, b2, b3,
                                bbase + (uint32_t)(bt * 16 * BANK_RS + ks * 32));
                    #pragma unroll
                    for (int mt = 0; mt < 4; ++mt) {
                        mma16816(d[mt][2 * bt],     a[mt], b0, b2);
                        mma16816(d[mt][2 * bt + 1], a[mt], b1, b3);
                    }
                }
            }
            __syncthreads();   // all warps done reading buf before refill
        }

        // ---- Epilogue: max over this warp's 64 bank rows per query ----
        #pragma unroll
        for (int mt = 0; mt < 4; ++mt) {
            float mx0 = -3.0e38f, mx1 = -3.0e38f;   // query rows r, r+8
            #pragma unroll
            for (int nt = 0; nt < 8; ++nt) {
                mx0 = fmaxf(mx0, fmaxf(d[mt][nt][0], d[mt][nt][1]));
                mx1 = fmaxf(mx1, fmaxf(d[mt][nt][2], d[mt][nt][3]));
            }
            mx0 = fmaxf(mx0, __shfl_xor_sync(0xFFFFFFFFu, mx0, 1));
            mx0 = fmaxf(mx0, __shfl_xor_sync(0xFFFFFFFFu, mx0, 2));
            mx1 = fmaxf(mx1, __shfl_xor_sync(0xFFFFFFFFu, mx1, 1));
            mx1 = fmaxf(mx1, __shfl_xor_sync(0xFFFFFFFFu, mx1, 2));
            if ((lane & 3) == 0) {
                int q0 = pass * MEGA + wm * 64 + mt * 16 + (lane >> 2);
                unsigned k0 = __float_as_uint(mx0);
                k0 = (k0 & 0x80000000u) ? ~k0 : (k0 | 0x80000000u);
                unsigned k1 = __float_as_uint(mx1);
                k1 = (k1 & 0x80000000u) ? ~k1 : (k1 | 0x80000000u);
                atomicMax(&g_key[q0], k0);
                atomicMax(&g_key[q0 + 8], k1);
            }
        }
    }
}

// ============================================================================
// Kernel 3: decode keys -> min distances
// ============================================================================
__global__ void final_kernel(float* __restrict__ out) {
    int b = blockIdx.x * blockDim.x + threadIdx.x;
    if (b < NQ) {
        unsigned key = g_key[b];
        unsigned bits = (key & 0x80000000u) ? (key ^ 0x80000000u) : ~key;
        float xy = __uint_as_float(bits);
        out[b] = sqrtf(fmaxf(2.0f - 2.0f * xy, 1e-12f));
    }
}

// ============================================================================
// Launch
// ============================================================================
extern "C" void kernel_launch(void* const* d_in, const int* in_sizes, int n_in,
                              void* d_out, int out_size) {
    const float* feat = (const float*)d_in[0];
    const float* bank = (const float*)d_in[1];
    if (n_in >= 2 && in_sizes[0] != NQ * DDIM) {   // robust to input ordering
        feat = (const float*)d_in[1];
        bank = (const float*)d_in[0];
    }
    float* out = (float*)d_out;

    cudaFuncSetAttribute(patchcore_main, cudaFuncAttributeMaxDynamicSharedMemorySize, SMEM_TOTAL);

    prep_kernel<<<NQ, 128>>>(feat);
    patchcore_main<<<MROWS / BANK_TILE, 256, SMEM_TOTAL>>>(bank);
    final_kernel<<<1, NQ>>>(out);
}